// round 8
// baseline (speedup 1.0000x reference)
#include <cuda_runtime.h>
#include <cuda_bf16.h>

// Calc_Xi_And_LogLikelihood
//   mu, sigma, eps : float32 [64, 16, 200, 64]
//   xi  = mu + (sigma + 1e-5) * eps                 -> first 13,107,200 floats of d_out
//   LL[bs,nc] = -0.5*sum eps^2 - sum log s - TS*(D/2)*log(2*pi)  -> next 1024 floats
//   (z = (xi-mu)/s == eps analytically; fp32 delta ~1e-4 abs on |LL|~5e3, far under tol)
//
// Geometry: SINGLE-WAVE residency. 1024 CTAs x 160 threads, 8 CTAs/SM allowed
// -> capacity 148*8 = 1184 >= 1024, so every CTA is resident from t=0 and the
// 1.73-wave quantization of the 320-thread variant (grid/592) disappears;
// per-SM imbalance is only 7-vs-6.92 CTAs (~1.2%).
// Memory path (best known from R5): plain float4 loads, __stcs streaming
// stores (xi never re-read during timing -> keep L2 for the input streams).
// Log trick: sum(log s) = sum(exponent)*ln2 + sum log(prod-of-4 mantissas);
// exponents accumulate as ints on the ALU pipe, one deg-6 poly per float4.

#define BS_ 64
#define NC_ 16
#define TS_ 200
#define D_  64

constexpr int ROW_ELEMS  = TS_ * D_;        // 12800 contiguous floats per (bs,nc)
constexpr int ROWS       = BS_ * NC_;       // 1024
constexpr int VEC        = ROW_ELEMS / 4;   // 3200 float4 per row
constexpr int THREADS    = 160;             // 5 warps
constexpr int PER_THREAD = VEC / THREADS;   // 20, exact
constexpr int NWARPS     = THREADS / 32;    // 5

constexpr float LL_CONST = 11762.413225019809f;   // TS*(D/2)*log(2*pi)
constexpr float LN2      = 0.69314718055994531f;

__global__ __launch_bounds__(THREADS, 8)
void calc_xi_ll_kernel(const float* __restrict__ mu,
                       const float* __restrict__ sigma,
                       const float* __restrict__ eps,
                       float* __restrict__ xi,
                       float* __restrict__ ll) {
    const int row = blockIdx.x;                       // (bs*NC + nc)
    const size_t base = (size_t)row * VEC;            // float4 index

    const float4* __restrict__ mu4 = (const float4*)mu  + base;
    const float4* __restrict__ sg4 = (const float4*)sigma + base;
    const float4* __restrict__ ep4 = (const float4*)eps + base;
    float4* __restrict__ xi4       = (float4*)xi + base;

    // Dual accumulators to halve the serial FMA chain length
    float ss0 = 0.0f, ss1 = 0.0f;    // sum eps^2
    float ls0 = 0.0f, ls1 = 0.0f;    // sum ln(mantissa products)
    int   ksum = 0;                  // sum of exponents (ALU pipe)

    #pragma unroll 4
    for (int j = 0; j < PER_THREAD; j++) {
        const int i = threadIdx.x + j * THREADS;
        float4 m = mu4[i];
        float4 g = sg4[i];
        float4 e = ep4[i];

        float sx = g.x + 1e-5f;
        float sy = g.y + 1e-5f;
        float sz = g.z + 1e-5f;
        float sw = g.w + 1e-5f;

        float4 o;
        o.x = fmaf(sx, e.x, m.x);
        o.y = fmaf(sy, e.y, m.y);
        o.z = fmaf(sz, e.z, m.z);
        o.w = fmaf(sw, e.w, m.w);
        __stcs(&xi4[i], o);                           // streaming store

        ss0 = fmaf(e.x, e.x, ss0);
        ss1 = fmaf(e.y, e.y, ss1);
        ss0 = fmaf(e.z, e.z, ss0);
        ss1 = fmaf(e.w, e.w, ss1);

        // Strip exponents (ALU pipe), keep mantissas in [2/3, 4/3)
        int bx = __float_as_int(sx); int ex = (bx - 0x3f2aaaab) & 0xff800000;
        int by = __float_as_int(sy); int ey = (by - 0x3f2aaaab) & 0xff800000;
        int bz = __float_as_int(sz); int ez = (bz - 0x3f2aaaab) & 0xff800000;
        int bw = __float_as_int(sw); int ew = (bw - 0x3f2aaaab) & 0xff800000;
        ksum += (ex >> 23) + (ey >> 23) + (ez >> 23) + (ew >> 23);

        float p = (__int_as_float(bx - ex) * __int_as_float(by - ey)) *
                  (__int_as_float(bz - ez) * __int_as_float(bw - ew));
        // p in [0.198, 3.16]; one more exponent strip, then one poly-log
        int bp = __float_as_int(p); int ep = (bp - 0x3f2aaaab) & 0xff800000;
        ksum += (ep >> 23);
        float t = __int_as_float(bp - ep) - 1.0f;     // t in [-1/3, 1/3)
        // ln(1+t) = t + t^2 * q(t),  q = -1/2 + t/3 - t^2/4 + t^3/5 - t^4/6
        float q = -0.16666667f;
        q = fmaf(q, t,  0.20000000f);
        q = fmaf(q, t, -0.25000000f);
        q = fmaf(q, t,  0.33333333f);
        q = fmaf(q, t, -0.50000000f);
        ls0 += t;
        ls1 = fmaf(q, t * t, ls1);
    }

    float ss   = ss0 + ss1;
    float lsum = fmaf((float)ksum, LN2, ls0 + ls1);

    // Intra-warp tree reduce (two scalars)
    #pragma unroll
    for (int off = 16; off > 0; off >>= 1) {
        ss   += __shfl_down_sync(0xffffffffu, ss, off);
        lsum += __shfl_down_sync(0xffffffffu, lsum, off);
    }

    __shared__ float s_ss[NWARPS];
    __shared__ float s_ls[NWARPS];
    const int wid = threadIdx.x >> 5;
    const int lid = threadIdx.x & 31;
    if (lid == 0) { s_ss[wid] = ss; s_ls[wid] = lsum; }
    __syncthreads();

    if (wid == 0) {
        ss   = (lid < NWARPS) ? s_ss[lid] : 0.0f;
        lsum = (lid < NWARPS) ? s_ls[lid] : 0.0f;
        #pragma unroll
        for (int off = 4; off > 0; off >>= 1) {
            ss   += __shfl_down_sync(0xffffffffu, ss, off);
            lsum += __shfl_down_sync(0xffffffffu, lsum, off);
        }
        if (lid == 0) {
            ll[row] = fmaf(-0.5f, ss, -lsum) - LL_CONST;
        }
    }
}

extern "C" void kernel_launch(void* const* d_in, const int* in_sizes, int n_in,
                              void* d_out, int out_size) {
    const float* mu    = (const float*)d_in[0];
    const float* sigma = (const float*)d_in[1];
    const float* eps   = (const float*)d_in[2];
    float* xi = (float*)d_out;
    float* ll = xi + (size_t)ROWS * ROW_ELEMS;   // LL follows xi in the output buffer

    calc_xi_ll_kernel<<<ROWS, THREADS>>>(mu, sigma, eps, xi, ll);
}

// round 9
// speedup vs baseline: 1.0164x; 1.0164x over previous
#include <cuda_runtime.h>
#include <cuda_bf16.h>

// Calc_Xi_And_LogLikelihood
//   mu, sigma, eps : float32 [64, 16, 200, 64]
//   xi  = mu + (sigma + 1e-5) * eps                 -> first 13,107,200 floats of d_out
//   LL[bs,nc] = -0.5*sum eps^2 - sum log s - TS*(D/2)*log(2*pi)  -> next 1024 floats
//   (z = (xi-mu)/s == eps analytically; fp32 delta ~1e-4 abs on |LL|~5e3, far under tol)
//
// Converged configuration (best across R2-R8 sweeps):
//  * one CTA per row: 1024 CTAs x 320 threads, __launch_bounds__(320,4),
//    10 uniform float4 iterations, unroll 5. (Single-wave 160-thr and 2-CTA/row
//    variants measured SLOWER; L2 evict_last pinning measured NO gain.)
//  * plain float4 loads; __stcs streaming stores — xi is never re-read during
//    timing, keeping it out of L2 preserves input residency (+9% DRAM util, R5).
//  * steady state is DRAM-period-bound: 209 MB/replay at ~6 TB/s sustained;
//    this config sits ~1us from that floor.
// Log trick: sum(log s) = sum(exponent)*ln2 + sum log(prod-of-4 mantissas);
// exponents accumulate as ints on the ALU pipe, one deg-6 poly per float4.
// Dual accumulators halve the serial FMA chain in the hot loop.

#define BS_ 64
#define NC_ 16
#define TS_ 200
#define D_  64

constexpr int ROW_ELEMS  = TS_ * D_;        // 12800 contiguous floats per (bs,nc)
constexpr int ROWS       = BS_ * NC_;       // 1024
constexpr int VEC        = ROW_ELEMS / 4;   // 3200 float4 per row
constexpr int THREADS    = 320;
constexpr int PER_THREAD = VEC / THREADS;   // 10, exact
constexpr int NWARPS     = THREADS / 32;    // 10

constexpr float LL_CONST = 11762.413225019809f;   // TS*(D/2)*log(2*pi)
constexpr float LN2      = 0.69314718055994531f;

__global__ __launch_bounds__(THREADS, 4)
void calc_xi_ll_kernel(const float* __restrict__ mu,
                       const float* __restrict__ sigma,
                       const float* __restrict__ eps,
                       float* __restrict__ xi,
                       float* __restrict__ ll) {
    const int row = blockIdx.x;                       // (bs*NC + nc)
    const size_t base = (size_t)row * VEC;            // float4 index

    const float4* __restrict__ mu4 = (const float4*)mu  + base;
    const float4* __restrict__ sg4 = (const float4*)sigma + base;
    const float4* __restrict__ ep4 = (const float4*)eps + base;
    float4* __restrict__ xi4       = (float4*)xi + base;

    // Dual accumulators to halve the serial FMA chain length
    float ss0 = 0.0f, ss1 = 0.0f;    // sum eps^2
    float ls0 = 0.0f, ls1 = 0.0f;    // sum ln(mantissa products)
    int   ksum = 0;                  // sum of exponents (ALU pipe)

    #pragma unroll 5
    for (int j = 0; j < PER_THREAD; j++) {
        const int i = threadIdx.x + j * THREADS;
        float4 m = mu4[i];
        float4 g = sg4[i];
        float4 e = ep4[i];

        float sx = g.x + 1e-5f;
        float sy = g.y + 1e-5f;
        float sz = g.z + 1e-5f;
        float sw = g.w + 1e-5f;

        float4 o;
        o.x = fmaf(sx, e.x, m.x);
        o.y = fmaf(sy, e.y, m.y);
        o.z = fmaf(sz, e.z, m.z);
        o.w = fmaf(sw, e.w, m.w);
        __stcs(&xi4[i], o);                           // streaming store

        ss0 = fmaf(e.x, e.x, ss0);
        ss1 = fmaf(e.y, e.y, ss1);
        ss0 = fmaf(e.z, e.z, ss0);
        ss1 = fmaf(e.w, e.w, ss1);

        // Strip exponents (ALU pipe), keep mantissas in [2/3, 4/3)
        int bx = __float_as_int(sx); int ex = (bx - 0x3f2aaaab) & 0xff800000;
        int by = __float_as_int(sy); int ey = (by - 0x3f2aaaab) & 0xff800000;
        int bz = __float_as_int(sz); int ez = (bz - 0x3f2aaaab) & 0xff800000;
        int bw = __float_as_int(sw); int ew = (bw - 0x3f2aaaab) & 0xff800000;
        ksum += (ex >> 23) + (ey >> 23) + (ez >> 23) + (ew >> 23);

        float p = (__int_as_float(bx - ex) * __int_as_float(by - ey)) *
                  (__int_as_float(bz - ez) * __int_as_float(bw - ew));
        // p in [0.198, 3.16]; one more exponent strip, then one poly-log
        int bp = __float_as_int(p); int ep = (bp - 0x3f2aaaab) & 0xff800000;
        ksum += (ep >> 23);
        float t = __int_as_float(bp - ep) - 1.0f;     // t in [-1/3, 1/3)
        // ln(1+t) = t + t^2 * q(t),  q = -1/2 + t/3 - t^2/4 + t^3/5 - t^4/6
        float q = -0.16666667f;
        q = fmaf(q, t,  0.20000000f);
        q = fmaf(q, t, -0.25000000f);
        q = fmaf(q, t,  0.33333333f);
        q = fmaf(q, t, -0.50000000f);
        ls0 += t;
        ls1 = fmaf(q, t * t, ls1);
    }

    float ss   = ss0 + ss1;
    float lsum = fmaf((float)ksum, LN2, ls0 + ls1);

    // Intra-warp tree reduce (two scalars)
    #pragma unroll
    for (int off = 16; off > 0; off >>= 1) {
        ss   += __shfl_down_sync(0xffffffffu, ss, off);
        lsum += __shfl_down_sync(0xffffffffu, lsum, off);
    }

    __shared__ float s_ss[NWARPS];
    __shared__ float s_ls[NWARPS];
    const int wid = threadIdx.x >> 5;
    const int lid = threadIdx.x & 31;
    if (lid == 0) { s_ss[wid] = ss; s_ls[wid] = lsum; }
    __syncthreads();

    if (wid == 0) {
        ss   = (lid < NWARPS) ? s_ss[lid] : 0.0f;
        lsum = (lid < NWARPS) ? s_ls[lid] : 0.0f;
        #pragma unroll
        for (int off = 8; off > 0; off >>= 1) {
            ss   += __shfl_down_sync(0xffffffffu, ss, off);
            lsum += __shfl_down_sync(0xffffffffu, lsum, off);
        }
        if (lid == 0) {
            ll[row] = fmaf(-0.5f, ss, -lsum) - LL_CONST;
        }
    }
}

extern "C" void kernel_launch(void* const* d_in, const int* in_sizes, int n_in,
                              void* d_out, int out_size) {
    const float* mu    = (const float*)d_in[0];
    const float* sigma = (const float*)d_in[1];
    const float* eps   = (const float*)d_in[2];
    float* xi = (float*)d_out;
    float* ll = xi + (size_t)ROWS * ROW_ELEMS;   // LL follows xi in the output buffer

    calc_xi_ll_kernel<<<ROWS, THREADS>>>(mu, sigma, eps, xi, ll);
}

// round 10
// speedup vs baseline: 1.0226x; 1.0061x over previous
#include <cuda_runtime.h>
#include <cuda_bf16.h>

// Calc_Xi_And_LogLikelihood
//   mu, sigma, eps : float32 [64, 16, 200, 64]
//   xi  = mu + (sigma + 1e-5) * eps                 -> first 13,107,200 floats of d_out
//   LL[bs,nc] = -0.5*sum eps^2 - sum log s - TS*(D/2)*log(2*pi)  -> next 1024 floats
//   (z = (xi-mu)/s == eps analytically; fp32 delta ~1e-4 abs on |LL|~5e3, far under tol)
//
// This is the byte-identical Round-5 artifact — the best-measured kernel
// (35.3us bench / 30.9us kernel / 75.6% DRAM). Every subsequent deviation
// (2048-CTA split, L2 evict_last pinning, 256-bit loads, 160-thread single
// wave, dual accumulators) measured neutral-to-worse. Resubmitted verbatim to
// discriminate instruction-schedule sensitivity from run-to-run variance.
//
// Geometry: one CTA per (bs,nc) row, 320 threads x 10 uniform float4 iters.
// Stores use __stcs (evict-first streaming): the xi write stream is never
// re-read during timing, so keeping it out of L2 preserves L2 residency of the
// graph-invariant inputs across replays.
// Log trick: sum(log s) = sum(exponent)*ln2 + sum log(prod-of-4 mantissas);
// exponents accumulate as ints on the ALU pipe, one poly-log per float4.

#define BS_ 64
#define NC_ 16
#define TS_ 200
#define D_  64

constexpr int ROW_ELEMS  = TS_ * D_;        // 12800 contiguous floats per (bs,nc)
constexpr int ROWS       = BS_ * NC_;       // 1024
constexpr int VEC        = ROW_ELEMS / 4;   // 3200 float4 per row
constexpr int THREADS    = 320;
constexpr int PER_THREAD = VEC / THREADS;   // 10, exact
constexpr int NWARPS     = THREADS / 32;    // 10

constexpr float LL_CONST = 11762.413225019809f;   // TS*(D/2)*log(2*pi)
constexpr float LN2      = 0.69314718055994531f;

__global__ __launch_bounds__(THREADS, 4)
void calc_xi_ll_kernel(const float* __restrict__ mu,
                       const float* __restrict__ sigma,
                       const float* __restrict__ eps,
                       float* __restrict__ xi,
                       float* __restrict__ ll) {
    const int row = blockIdx.x;                       // (bs*NC + nc)
    const size_t base = (size_t)row * VEC;            // float4 index

    const float4* __restrict__ mu4 = (const float4*)mu  + base;
    const float4* __restrict__ sg4 = (const float4*)sigma + base;
    const float4* __restrict__ ep4 = (const float4*)eps + base;
    float4* __restrict__ xi4       = (float4*)xi + base;

    float ss   = 0.0f;   // sum eps^2
    float ls   = 0.0f;   // sum ln(mantissa products)
    int   ksum = 0;      // sum of exponents

    #pragma unroll 5
    for (int j = 0; j < PER_THREAD; j++) {
        const int i = threadIdx.x + j * THREADS;
        float4 m = mu4[i];
        float4 g = sg4[i];
        float4 e = ep4[i];

        float sx = g.x + 1e-5f;
        float sy = g.y + 1e-5f;
        float sz = g.z + 1e-5f;
        float sw = g.w + 1e-5f;

        float4 o;
        o.x = fmaf(sx, e.x, m.x);
        o.y = fmaf(sy, e.y, m.y);
        o.z = fmaf(sz, e.z, m.z);
        o.w = fmaf(sw, e.w, m.w);
        __stcs(&xi4[i], o);                           // streaming store: keep L2 for inputs

        ss = fmaf(e.x, e.x, ss);
        ss = fmaf(e.y, e.y, ss);
        ss = fmaf(e.z, e.z, ss);
        ss = fmaf(e.w, e.w, ss);

        // Strip exponents (ALU pipe), keep mantissas in [2/3, 4/3)
        int bx = __float_as_int(sx); int ex = (bx - 0x3f2aaaab) & 0xff800000;
        int by = __float_as_int(sy); int ey = (by - 0x3f2aaaab) & 0xff800000;
        int bz = __float_as_int(sz); int ez = (bz - 0x3f2aaaab) & 0xff800000;
        int bw = __float_as_int(sw); int ew = (bw - 0x3f2aaaab) & 0xff800000;
        ksum += (ex >> 23) + (ey >> 23) + (ez >> 23) + (ew >> 23);

        float p = (__int_as_float(bx - ex) * __int_as_float(by - ey)) *
                  (__int_as_float(bz - ez) * __int_as_float(bw - ew));
        // p in [0.198, 3.16]; one more exponent strip, then one poly-log
        int bp = __float_as_int(p); int ep = (bp - 0x3f2aaaab) & 0xff800000;
        ksum += (ep >> 23);
        float t = __int_as_float(bp - ep) - 1.0f;     // t in [-1/3, 1/3)
        // ln(1+t) = t + t^2 * q(t),  q = -1/2 + t/3 - t^2/4 + t^3/5 - t^4/6
        float q = -0.16666667f;
        q = fmaf(q, t,  0.20000000f);
        q = fmaf(q, t, -0.25000000f);
        q = fmaf(q, t,  0.33333333f);
        q = fmaf(q, t, -0.50000000f);
        ls += t;
        ls = fmaf(q, t * t, ls);
    }

    float lsum = fmaf((float)ksum, LN2, ls);

    // Intra-warp tree reduce (two scalars)
    #pragma unroll
    for (int off = 16; off > 0; off >>= 1) {
        ss   += __shfl_down_sync(0xffffffffu, ss, off);
        lsum += __shfl_down_sync(0xffffffffu, lsum, off);
    }

    __shared__ float s_ss[NWARPS];
    __shared__ float s_ls[NWARPS];
    const int wid = threadIdx.x >> 5;
    const int lid = threadIdx.x & 31;
    if (lid == 0) { s_ss[wid] = ss; s_ls[wid] = lsum; }
    __syncthreads();

    if (wid == 0) {
        ss   = (lid < NWARPS) ? s_ss[lid] : 0.0f;
        lsum = (lid < NWARPS) ? s_ls[lid] : 0.0f;
        #pragma unroll
        for (int off = 8; off > 0; off >>= 1) {
            ss   += __shfl_down_sync(0xffffffffu, ss, off);
            lsum += __shfl_down_sync(0xffffffffu, lsum, off);
        }
        if (lid == 0) {
            ll[row] = fmaf(-0.5f, ss, -lsum) - LL_CONST;
        }
    }
}

extern "C" void kernel_launch(void* const* d_in, const int* in_sizes, int n_in,
                              void* d_out, int out_size) {
    const float* mu    = (const float*)d_in[0];
    const float* sigma = (const float*)d_in[1];
    const float* eps   = (const float*)d_in[2];
    float* xi = (float*)d_out;
    float* ll = xi + (size_t)ROWS * ROW_ELEMS;   // LL follows xi in the output buffer

    calc_xi_ll_kernel<<<ROWS, THREADS>>>(mu, sigma, eps, xi, ll);
}

// round 11
// speedup vs baseline: 1.0643x; 1.0408x over previous
#include <cuda_runtime.h>
#include <cuda_bf16.h>

// Calc_Xi_And_LogLikelihood — converged configuration (R5/R10 artifact + __ldg)
//   mu, sigma, eps : float32 [64, 16, 200, 64]
//   xi  = mu + (sigma + 1e-5) * eps                 -> first 13,107,200 floats of d_out
//   LL[bs,nc] = -0.5*sum eps^2 - sum log s - TS*(D/2)*log(2*pi)  -> next 1024 floats
//   (z = (xi-mu)/s == eps analytically; fp32 delta ~1e-4 abs on |LL|~5e3, far under tol)
//
// Evidence summary (R2-R10):
//  * Kernel window is reproducibly 30.9-31.1us at 75% DRAM with this exact
//    geometry/schedule; 75% is the HBM mixed-stream (3:1 R:W turnaround)
//    ceiling, so this is the floor. Bench metric adds ~4.5us fixed replay gap
//    and +/-1.5us harness noise.
//  * Measured NO-GAIN/WORSE: 2048-CTA split, L2 evict_last pinning, 256-bit
//    loads, 160-thread single-wave, dual accumulators.
//  * Measured WINS kept: __stcs streaming stores (+9% DRAM util), 320thr/occ4,
//    unroll 5, exponent-stripped 4:1-batched poly-log (no MUFU, no div).
// Only change this round: __ldg on input loads to guarantee the .nc read-only
// path in SASS.

#define BS_ 64
#define NC_ 16
#define TS_ 200
#define D_  64

constexpr int ROW_ELEMS  = TS_ * D_;        // 12800 contiguous floats per (bs,nc)
constexpr int ROWS       = BS_ * NC_;       // 1024
constexpr int VEC        = ROW_ELEMS / 4;   // 3200 float4 per row
constexpr int THREADS    = 320;
constexpr int PER_THREAD = VEC / THREADS;   // 10, exact
constexpr int NWARPS     = THREADS / 32;    // 10

constexpr float LL_CONST = 11762.413225019809f;   // TS*(D/2)*log(2*pi)
constexpr float LN2      = 0.69314718055994531f;

__global__ __launch_bounds__(THREADS, 4)
void calc_xi_ll_kernel(const float* __restrict__ mu,
                       const float* __restrict__ sigma,
                       const float* __restrict__ eps,
                       float* __restrict__ xi,
                       float* __restrict__ ll) {
    const int row = blockIdx.x;                       // (bs*NC + nc)
    const size_t base = (size_t)row * VEC;            // float4 index

    const float4* __restrict__ mu4 = (const float4*)mu  + base;
    const float4* __restrict__ sg4 = (const float4*)sigma + base;
    const float4* __restrict__ ep4 = (const float4*)eps + base;
    float4* __restrict__ xi4       = (float4*)xi + base;

    float ss   = 0.0f;   // sum eps^2
    float ls   = 0.0f;   // sum ln(mantissa products)
    int   ksum = 0;      // sum of exponents

    #pragma unroll 5
    for (int j = 0; j < PER_THREAD; j++) {
        const int i = threadIdx.x + j * THREADS;
        float4 m = __ldg(&mu4[i]);
        float4 g = __ldg(&sg4[i]);
        float4 e = __ldg(&ep4[i]);

        float sx = g.x + 1e-5f;
        float sy = g.y + 1e-5f;
        float sz = g.z + 1e-5f;
        float sw = g.w + 1e-5f;

        float4 o;
        o.x = fmaf(sx, e.x, m.x);
        o.y = fmaf(sy, e.y, m.y);
        o.z = fmaf(sz, e.z, m.z);
        o.w = fmaf(sw, e.w, m.w);
        __stcs(&xi4[i], o);                           // streaming store: keep L2 for inputs

        ss = fmaf(e.x, e.x, ss);
        ss = fmaf(e.y, e.y, ss);
        ss = fmaf(e.z, e.z, ss);
        ss = fmaf(e.w, e.w, ss);

        // Strip exponents (ALU pipe), keep mantissas in [2/3, 4/3)
        int bx = __float_as_int(sx); int ex = (bx - 0x3f2aaaab) & 0xff800000;
        int by = __float_as_int(sy); int ey = (by - 0x3f2aaaab) & 0xff800000;
        int bz = __float_as_int(sz); int ez = (bz - 0x3f2aaaab) & 0xff800000;
        int bw = __float_as_int(sw); int ew = (bw - 0x3f2aaaab) & 0xff800000;
        ksum += (ex >> 23) + (ey >> 23) + (ez >> 23) + (ew >> 23);

        float p = (__int_as_float(bx - ex) * __int_as_float(by - ey)) *
                  (__int_as_float(bz - ez) * __int_as_float(bw - ew));
        // p in [0.198, 3.16]; one more exponent strip, then one poly-log
        int bp = __float_as_int(p); int ep = (bp - 0x3f2aaaab) & 0xff800000;
        ksum += (ep >> 23);
        float t = __int_as_float(bp - ep) - 1.0f;     // t in [-1/3, 1/3)
        // ln(1+t) = t + t^2 * q(t),  q = -1/2 + t/3 - t^2/4 + t^3/5 - t^4/6
        float q = -0.16666667f;
        q = fmaf(q, t,  0.20000000f);
        q = fmaf(q, t, -0.25000000f);
        q = fmaf(q, t,  0.33333333f);
        q = fmaf(q, t, -0.50000000f);
        ls += t;
        ls = fmaf(q, t * t, ls);
    }

    float lsum = fmaf((float)ksum, LN2, ls);

    // Intra-warp tree reduce (two scalars)
    #pragma unroll
    for (int off = 16; off > 0; off >>= 1) {
        ss   += __shfl_down_sync(0xffffffffu, ss, off);
        lsum += __shfl_down_sync(0xffffffffu, lsum, off);
    }

    __shared__ float s_ss[NWARPS];
    __shared__ float s_ls[NWARPS];
    const int wid = threadIdx.x >> 5;
    const int lid = threadIdx.x & 31;
    if (lid == 0) { s_ss[wid] = ss; s_ls[wid] = lsum; }
    __syncthreads();

    if (wid == 0) {
        ss   = (lid < NWARPS) ? s_ss[lid] : 0.0f;
        lsum = (lid < NWARPS) ? s_ls[lid] : 0.0f;
        #pragma unroll
        for (int off = 8; off > 0; off >>= 1) {
            ss   += __shfl_down_sync(0xffffffffu, ss, off);
            lsum += __shfl_down_sync(0xffffffffu, lsum, off);
        }
        if (lid == 0) {
            ll[row] = fmaf(-0.5f, ss, -lsum) - LL_CONST;
        }
    }
}

extern "C" void kernel_launch(void* const* d_in, const int* in_sizes, int n_in,
                              void* d_out, int out_size) {
    const float* mu    = (const float*)d_in[0];
    const float* sigma = (const float*)d_in[1];
    const float* eps   = (const float*)d_in[2];
    float* xi = (float*)d_out;
    float* ll = xi + (size_t)ROWS * ROW_ELEMS;   // LL follows xi in the output buffer

    calc_xi_ll_kernel<<<ROWS, THREADS>>>(mu, sigma, eps, xi, ll);
}